// round 2
// baseline (speedup 1.0000x reference)
#include <cuda_runtime.h>
#include <math.h>

#define NN 100000
#define EE 3200000
#define HIDD 64
#define BN_EPS 1e-5f

// ---- scratch (device globals; allocation-free) ----
__device__ int g_is64;
__device__ __align__(16) int   g_src[EE];
__device__ __align__(16) int   g_dst[EE];
__device__ __align__(16) int   g_deg[NN];
__device__ __align__(16) int   g_off[NN + 1];
__device__ __align__(16) int   g_cur[NN];
__device__ __align__(16) float g_dinv[NN];
__device__ __align__(16) int   g_csr[EE];
__device__ __align__(16) float g_hs[NN * HIDD];
__device__ __align__(16) float g_act[NN * HIDD];
__device__ __align__(16) float g_h3[NN];

// ---- detect edge_index dtype: int64 => odd 32-bit words all zero ----
__global__ void detect_kernel(const int* __restrict__ ei_w) {
    __shared__ int sor;
    if (threadIdx.x == 0) sor = 0;
    __syncthreads();
    int acc = 0;
    // scan first 1M pairs (8 MB) — safe under either dtype (buffer >= 25.6 MB)
    for (int i = threadIdx.x; i < (1 << 20); i += blockDim.x)
        acc |= ei_w[2 * i + 1];
    if (acc) atomicOr(&sor, 1);
    __syncthreads();
    if (threadIdx.x == 0) g_is64 = (sor == 0) ? 1 : 0;
}

// ---- normalize edges to int32 device arrays ----
__global__ void convert_edges(const void* __restrict__ ei) {
    int e = blockIdx.x * blockDim.x + threadIdx.x;
    if (e >= EE) return;
    if (g_is64) {
        const long long* p = (const long long*)ei;
        g_src[e] = (int)p[e];
        g_dst[e] = (int)p[e + EE];
    } else {
        const int* p = (const int*)ei;
        g_src[e] = p[e];
        g_dst[e] = p[e + EE];
    }
}

// ---- zero the per-launch counters ----
__global__ void zero_counts() {
    int i = blockIdx.x * blockDim.x + threadIdx.x;
    if (i < NN) { g_deg[i] = 0; g_cur[i] = 0; }
}

// ---- degree count on dst ----
__global__ void count_kernel() {
    int e = blockIdx.x * blockDim.x + threadIdx.x;
    int d = g_dst[e];
    if ((unsigned)d < NN) atomicAdd(&g_deg[d], 1);
}

// ---- single-block exclusive scan over degrees; also dinv = rsqrt(deg+1) ----
__global__ void scan_kernel() {
    __shared__ int ss[1024];
    int t = threadIdx.x;
    const int PER = (NN + 1023) / 1024;  // 98
    int start = t * PER;
    int end = start + PER; if (end > NN) end = NN;
    int s = 0;
    for (int i = start; i < end; i++) s += g_deg[i];
    ss[t] = s;
    __syncthreads();
    for (int off = 1; off < 1024; off <<= 1) {
        int v = ss[t];
        int a = (t >= off) ? ss[t - off] : 0;
        __syncthreads();
        ss[t] = v + a;
        __syncthreads();
    }
    int base = (t > 0) ? ss[t - 1] : 0;
    for (int i = start; i < end; i++) {
        g_off[i] = base;
        int d = g_deg[i];
        base += d;
        g_dinv[i] = rsqrtf((float)d + 1.0f);
    }
    if (t == 1023) g_off[NN] = ss[1023];
}

// ---- CSR fill: place src ids grouped by dst ----
__global__ void fill_kernel() {
    int e = blockIdx.x * blockDim.x + threadIdx.x;
    int d = g_dst[e];
    if ((unsigned)d >= NN) return;
    int s = g_src[e];
    if ((unsigned)s >= NN) return;
    int pos = atomicAdd(&g_cur[d], 1);
    g_csr[g_off[d] + pos] = s;
}

// ---- tiled GEMM: out[n, 64] = (X[n, :K] @ W[K, 64]) * dinv[n] ----
template <int K>
__global__ void __launch_bounds__(256) gemm_dinv(const float* __restrict__ X,
                                                 const float* __restrict__ W,
                                                 float* __restrict__ out) {
    __shared__ float Xs[32][K];
    __shared__ float Ws[K][64];
    const int t = threadIdx.x;
    const int row0 = blockIdx.x * 32;

    for (int i = t; i < K * 16; i += 256)
        reinterpret_cast<float4*>(Ws)[i] = reinterpret_cast<const float4*>(W)[i];
    for (int i = t; i < 32 * (K / 4); i += 256) {
        int r = i / (K / 4), c = i % (K / 4);
        reinterpret_cast<float4*>(Xs[r])[c] =
            reinterpret_cast<const float4*>(X)[(size_t)(row0 + r) * (K / 4) + c];
    }
    __syncthreads();

    const int tx = t & 15;          // col group (float4): cols tx*4 .. tx*4+3
    const int r0 = (t >> 4) * 2;    // two rows per thread
    float4 a0 = make_float4(0.f, 0.f, 0.f, 0.f);
    float4 a1 = make_float4(0.f, 0.f, 0.f, 0.f);

#pragma unroll 16
    for (int k = 0; k < K; k++) {
        float4 w = reinterpret_cast<float4*>(Ws[k])[tx];
        float x0 = Xs[r0][k];
        float x1 = Xs[r0 + 1][k];
        a0.x = fmaf(x0, w.x, a0.x); a0.y = fmaf(x0, w.y, a0.y);
        a0.z = fmaf(x0, w.z, a0.z); a0.w = fmaf(x0, w.w, a0.w);
        a1.x = fmaf(x1, w.x, a1.x); a1.y = fmaf(x1, w.y, a1.y);
        a1.z = fmaf(x1, w.z, a1.z); a1.w = fmaf(x1, w.w, a1.w);
    }

    float d0 = g_dinv[row0 + r0];
    float d1 = g_dinv[row0 + r0 + 1];
    a0.x *= d0; a0.y *= d0; a0.z *= d0; a0.w *= d0;
    a1.x *= d1; a1.y *= d1; a1.z *= d1; a1.w *= d1;
    reinterpret_cast<float4*>(out)[(size_t)(row0 + r0) * 16 + tx] = a0;
    reinterpret_cast<float4*>(out)[(size_t)(row0 + r0 + 1) * 16 + tx] = a1;
}

// ---- gather aggregation + self-loop + bias + BN + ReLU, warp per node ----
__global__ void __launch_bounds__(256) gather_bn_relu(const float* __restrict__ hs,
                                                      float* __restrict__ out,
                                                      const float* __restrict__ b,
                                                      const float* __restrict__ g,
                                                      const float* __restrict__ beta,
                                                      const float* __restrict__ m,
                                                      const float* __restrict__ v) {
    int warp = threadIdx.x >> 5;
    int lane = threadIdx.x & 31;
    int node = blockIdx.x * 8 + warp;
    if (node >= NN) return;

    const float2* hs2 = reinterpret_cast<const float2*>(hs);
    float2 acc = hs2[(size_t)node * 32 + lane];   // self-loop term (already *dinv[node])
    int e0 = g_off[node], e1 = g_off[node + 1];
#pragma unroll 4
    for (int e = e0; e < e1; e++) {
        int s = g_csr[e];
        float2 xx = hs2[(size_t)s * 32 + lane];
        acc.x += xx.x; acc.y += xx.y;
    }
    float di = g_dinv[node];
    int k0 = lane * 2;
    float s0 = g[k0] * rsqrtf(v[k0] + BN_EPS);
    float s1 = g[k0 + 1] * rsqrtf(v[k0 + 1] + BN_EPS);
    float z0 = (acc.x * di + b[k0]     - m[k0])     * s0 + beta[k0];
    float z1 = (acc.y * di + b[k0 + 1] - m[k0 + 1]) * s1 + beta[k0 + 1];
    float2 o = make_float2(fmaxf(z0, 0.f), fmaxf(z1, 0.f));
    reinterpret_cast<float2*>(out)[(size_t)node * 32 + lane] = o;
}

// ---- layer 3 projection: h3[n] = dot(act[n,:], W3) * dinv[n], warp per node ----
__global__ void __launch_bounds__(256) dot3_kernel(const float* __restrict__ act,
                                                   const float* __restrict__ W3) {
    int warp = threadIdx.x >> 5;
    int lane = threadIdx.x & 31;
    int node = blockIdx.x * 8 + warp;
    if (node >= NN) return;
    const float2* a2 = reinterpret_cast<const float2*>(act);
    const float2* w2 = reinterpret_cast<const float2*>(W3);
    float2 xx = a2[(size_t)node * 32 + lane];
    float2 ww = w2[lane];
    float s = xx.x * ww.x + xx.y * ww.y;
#pragma unroll
    for (int o = 16; o > 0; o >>= 1) s += __shfl_xor_sync(0xffffffffu, s, o);
    if (lane == 0) g_h3[node] = s * g_dinv[node];
}

// ---- layer 3 gather + sigmoid, thread per node ----
__global__ void gather3_sigmoid(const float* __restrict__ b3, float* __restrict__ out) {
    int i = blockIdx.x * blockDim.x + threadIdx.x;
    if (i >= NN) return;
    float acc = g_h3[i];  // self-loop term
    int e0 = g_off[i], e1 = g_off[i + 1];
#pragma unroll 4
    for (int e = e0; e < e1; e++) acc += g_h3[g_csr[e]];
    float z = acc * g_dinv[i] + b3[0];
    out[i] = 1.0f / (1.0f + expf(-z));
}

extern "C" void kernel_launch(void* const* d_in, const int* in_sizes, int n_in,
                              void* d_out, int out_size) {
    const float* x   = (const float*)d_in[0];
    const void*  ei  = d_in[1];
    const float* W1  = (const float*)d_in[2];
    const float* b1  = (const float*)d_in[3];
    const float* W2  = (const float*)d_in[4];
    const float* b2  = (const float*)d_in[5];
    const float* W3  = (const float*)d_in[6];
    const float* b3  = (const float*)d_in[7];
    const float* g1  = (const float*)d_in[8];
    const float* be1 = (const float*)d_in[9];
    const float* m1  = (const float*)d_in[10];
    const float* v1  = (const float*)d_in[11];
    const float* g2  = (const float*)d_in[12];
    const float* be2 = (const float*)d_in[13];
    const float* m2  = (const float*)d_in[14];
    const float* v2  = (const float*)d_in[15];

    float *hs = nullptr, *act = nullptr;
    cudaGetSymbolAddress((void**)&hs, g_hs);
    cudaGetSymbolAddress((void**)&act, g_act);

    detect_kernel<<<1, 1024>>>((const int*)ei);
    convert_edges<<<EE / 256, 256>>>(ei);
    zero_counts<<<(NN + 255) / 256, 256>>>();
    count_kernel<<<EE / 256, 256>>>();
    scan_kernel<<<1, 1024>>>();
    fill_kernel<<<EE / 256, 256>>>();

    // layer 1: hs = (x @ W1) * dinv ; act = relu(bn(gather(hs) + b1))
    gemm_dinv<128><<<NN / 32, 256>>>(x, W1, hs);
    gather_bn_relu<<<NN / 8, 256>>>(hs, act, b1, g1, be1, m1, v1);

    // layer 2
    gemm_dinv<64><<<NN / 32, 256>>>(act, W2, hs);
    gather_bn_relu<<<NN / 8, 256>>>(hs, act, b2, g2, be2, m2, v2);

    // layer 3
    dot3_kernel<<<NN / 8, 256>>>(act, W3);
    gather3_sigmoid<<<(NN + 255) / 256, 256>>>(b3, (float*)d_out);
}

// round 3
// speedup vs baseline: 1.1356x; 1.1356x over previous
#include <cuda_runtime.h>
#include <math.h>

#define NN 100000
#define EE 3200000
#define HIDD 64
#define BN_EPS 1e-5f

// ---- scratch (device globals; allocation-free) ----
__device__ int g_is64;
__device__ __align__(16) int   g_src[EE];
__device__ __align__(16) int   g_dst[EE];
__device__ __align__(16) int   g_deg[NN];
__device__ __align__(16) int   g_off[NN + 1];
__device__ __align__(16) int   g_cur[NN];
__device__ __align__(16) float g_dinv[NN];
__device__ __align__(16) int   g_csr[EE];
__device__ __align__(16) float g_hs[NN * HIDD];
__device__ __align__(16) float g_act[NN * HIDD];
__device__ __align__(16) float g_h3[NN];

// ---- zero degree counters ----
__global__ void zero_deg() {
    int i = blockIdx.x * blockDim.x + threadIdx.x;
    if (i < NN) g_deg[i] = 0;
}

// ---- detect edge_index dtype: int64 => odd 32-bit words all zero ----
__global__ void detect_kernel(const int* __restrict__ ei_w) {
    __shared__ int sor;
    if (threadIdx.x == 0) sor = 0;
    __syncthreads();
    int acc = 0;
    for (int i = threadIdx.x; i < 8192; i += blockDim.x)
        acc |= ei_w[2 * i + 1];
    if (acc) atomicOr(&sor, 1);
    __syncthreads();
    if (threadIdx.x == 0) g_is64 = (sor == 0) ? 1 : 0;
}

// ---- normalize edges to int32 + degree count (fused) ----
__global__ void convert_count(const void* __restrict__ ei) {
    int e = blockIdx.x * blockDim.x + threadIdx.x;
    int s, d;
    if (g_is64) {
        const long long* p = (const long long*)ei;
        s = (int)p[e]; d = (int)p[e + EE];
    } else {
        const int* p = (const int*)ei;
        s = p[e]; d = p[e + EE];
    }
    g_src[e] = s;
    g_dst[e] = d;
    if ((unsigned)d < NN) atomicAdd(&g_deg[d], 1);
}

// ---- single-block scan: offsets, dinv, and cur=off init ----
__global__ void scan_kernel() {
    __shared__ int ss[1024];
    int t = threadIdx.x;
    const int PER = (NN + 1023) / 1024;  // 98
    int start = t * PER;
    int end = start + PER; if (end > NN) end = NN;
    int s = 0;
    for (int i = start; i < end; i++) s += g_deg[i];
    ss[t] = s;
    __syncthreads();
    for (int off = 1; off < 1024; off <<= 1) {
        int v = ss[t];
        int a = (t >= off) ? ss[t - off] : 0;
        __syncthreads();
        ss[t] = v + a;
        __syncthreads();
    }
    int base = (t > 0) ? ss[t - 1] : 0;
    for (int i = start; i < end; i++) {
        g_off[i] = base;
        g_cur[i] = base;
        int d = g_deg[i];
        base += d;
        g_dinv[i] = rsqrtf((float)d + 1.0f);
    }
    if (t == 1023) g_off[NN] = ss[1023];
}

// ---- CSR fill using cur (pre-initialized to off) ----
__global__ void fill_kernel() {
    int e = blockIdx.x * blockDim.x + threadIdx.x;
    int d = g_dst[e];
    if ((unsigned)d >= NN) return;
    int s = g_src[e];
    if ((unsigned)s >= NN) return;
    int pos = atomicAdd(&g_cur[d], 1);
    g_csr[pos] = s;
}

// ---- GEMM: out[n,64] = (X[n,:K] @ W[K,64]) * dinv[n]
// 64-row tiles, broadcast-x, FFMA2 packed fp32 math, conflict-free smem.
template <int K>
__global__ void __launch_bounds__(256) gemm_dinv(const float* __restrict__ X,
                                                 const float* __restrict__ W,
                                                 float* __restrict__ out) {
    __shared__ float Xs[64][68];   // padded: bank = (4r+k)%32, conflict-free across row groups
    __shared__ float Ws[64][64];
    const int t = threadIdx.x;
    const int lane = t & 31;
    const int w = t >> 5;
    const int row0 = blockIdx.x * 64;
    const int rbase = w * 8 + ((lane >> 4) << 2);  // 4 rows per thread
    const int c4 = lane & 15;                      // float4 column index (cols 4*c4..4*c4+3)

    unsigned long long acc[4][2];
#pragma unroll
    for (int j = 0; j < 4; j++) { acc[j][0] = 0ull; acc[j][1] = 0ull; }

    const int HALVES = K / 64;
    for (int h = 0; h < HALVES; h++) {
        // load W half [64][64]
#pragma unroll
        for (int p = 0; p < 4; p++) {
            int idx = t + p * 256;
            int kk = idx >> 4, q = idx & 15;
            reinterpret_cast<float4*>(&Ws[kk][0])[q] =
                reinterpret_cast<const float4*>(W)[(size_t)(h * 64 + kk) * 16 + q];
        }
        // load X half [64][64] (row-clamped)
#pragma unroll
        for (int p = 0; p < 4; p++) {
            int idx = t + p * 256;
            int r = idx >> 4, q = idx & 15;
            int gr = row0 + r; if (gr >= NN) gr = NN - 1;
            reinterpret_cast<float4*>(&Xs[r][0])[q] =
                reinterpret_cast<const float4*>(X)[(size_t)gr * (K / 4) + h * 16 + q];
        }
        __syncthreads();

        unsigned wb = (unsigned)__cvta_generic_to_shared(&Ws[0][c4 * 4]);
#pragma unroll 16
        for (int kk = 0; kk < 64; kk++) {
            unsigned long long w01, w23;
            asm("ld.shared.v2.u64 {%0, %1}, [%2];"
                : "=l"(w01), "=l"(w23) : "r"(wb + kk * 256));
#pragma unroll
            for (int j = 0; j < 4; j++) {
                float xv = Xs[rbase + j][kk];
                unsigned long long xx;
                asm("mov.b64 %0, {%1, %1};" : "=l"(xx) : "f"(xv));
                asm("fma.rn.f32x2 %0, %1, %2, %3;"
                    : "=l"(acc[j][0]) : "l"(xx), "l"(w01), "l"(acc[j][0]));
                asm("fma.rn.f32x2 %0, %1, %2, %3;"
                    : "=l"(acc[j][1]) : "l"(xx), "l"(w23), "l"(acc[j][1]));
            }
        }
        __syncthreads();
    }

#pragma unroll
    for (int j = 0; j < 4; j++) {
        int r = row0 + rbase + j;
        if (r < NN) {
            float d = g_dinv[r];
            float lo, hi;
            float4 o;
            asm("mov.b64 {%0, %1}, %2;" : "=f"(lo), "=f"(hi) : "l"(acc[j][0]));
            o.x = lo * d; o.y = hi * d;
            asm("mov.b64 {%0, %1}, %2;" : "=f"(lo), "=f"(hi) : "l"(acc[j][1]));
            o.z = lo * d; o.w = hi * d;
            reinterpret_cast<float4*>(out)[(size_t)r * 16 + c4] = o;
        }
    }
}

// ---- gather + self-loop + bias + BN + ReLU, warp per node ----
__global__ void __launch_bounds__(256) gather_bn_relu(const float* __restrict__ hs,
                                                      float* __restrict__ out,
                                                      const float* __restrict__ b,
                                                      const float* __restrict__ g,
                                                      const float* __restrict__ beta,
                                                      const float* __restrict__ m,
                                                      const float* __restrict__ v) {
    int warp = threadIdx.x >> 5;
    int lane = threadIdx.x & 31;
    int node = blockIdx.x * 8 + warp;
    if (node >= NN) return;

    const float2* hs2 = reinterpret_cast<const float2*>(hs);
    float2 acc = hs2[(size_t)node * 32 + lane];   // self-loop (already *dinv[node])
    int e0 = g_off[node], e1 = g_off[node + 1];
#pragma unroll 4
    for (int e = e0; e < e1; e++) {
        int s = g_csr[e];
        float2 xx = hs2[(size_t)s * 32 + lane];
        acc.x += xx.x; acc.y += xx.y;
    }
    float di = g_dinv[node];
    int k0 = lane * 2;
    float s0 = g[k0] * rsqrtf(v[k0] + BN_EPS);
    float s1 = g[k0 + 1] * rsqrtf(v[k0 + 1] + BN_EPS);
    float z0 = (acc.x * di + b[k0]     - m[k0])     * s0 + beta[k0];
    float z1 = (acc.y * di + b[k0 + 1] - m[k0 + 1]) * s1 + beta[k0 + 1];
    float2 o = make_float2(fmaxf(z0, 0.f), fmaxf(z1, 0.f));
    reinterpret_cast<float2*>(out)[(size_t)node * 32 + lane] = o;
}

// ---- layer-2 gather + BN + ReLU + fused W3 dot -> g_h3 (act never stored) ----
__global__ void __launch_bounds__(256) gather2_dot(const float* __restrict__ hs,
                                                   const float* __restrict__ b,
                                                   const float* __restrict__ g,
                                                   const float* __restrict__ beta,
                                                   const float* __restrict__ m,
                                                   const float* __restrict__ v,
                                                   const float* __restrict__ W3) {
    int warp = threadIdx.x >> 5;
    int lane = threadIdx.x & 31;
    int node = blockIdx.x * 8 + warp;
    if (node >= NN) return;

    const float2* hs2 = reinterpret_cast<const float2*>(hs);
    float2 acc = hs2[(size_t)node * 32 + lane];
    int e0 = g_off[node], e1 = g_off[node + 1];
#pragma unroll 4
    for (int e = e0; e < e1; e++) {
        int s = g_csr[e];
        float2 xx = hs2[(size_t)s * 32 + lane];
        acc.x += xx.x; acc.y += xx.y;
    }
    float di = g_dinv[node];
    int k0 = lane * 2;
    float s0 = g[k0] * rsqrtf(v[k0] + BN_EPS);
    float s1 = g[k0 + 1] * rsqrtf(v[k0 + 1] + BN_EPS);
    float z0 = (acc.x * di + b[k0]     - m[k0])     * s0 + beta[k0];
    float z1 = (acc.y * di + b[k0 + 1] - m[k0 + 1]) * s1 + beta[k0 + 1];
    float o0 = fmaxf(z0, 0.f), o1 = fmaxf(z1, 0.f);

    float2 w3 = reinterpret_cast<const float2*>(W3)[lane];
    float part = o0 * w3.x + o1 * w3.y;
#pragma unroll
    for (int o = 16; o > 0; o >>= 1) part += __shfl_xor_sync(0xffffffffu, part, o);
    if (lane == 0) g_h3[node] = part * di;
}

// ---- layer-3 gather + sigmoid, warp per node ----
__global__ void __launch_bounds__(256) gather3_sigmoid(const float* __restrict__ b3,
                                                       float* __restrict__ out) {
    int warp = threadIdx.x >> 5;
    int lane = threadIdx.x & 31;
    int node = blockIdx.x * 8 + warp;
    if (node >= NN) return;
    int e0 = g_off[node], e1 = g_off[node + 1];
    float a = 0.f;
    for (int e = e0 + lane; e < e1; e += 32) a += g_h3[g_csr[e]];
#pragma unroll
    for (int o = 16; o > 0; o >>= 1) a += __shfl_xor_sync(0xffffffffu, a, o);
    if (lane == 0) {
        float z = (a + g_h3[node]) * g_dinv[node] + b3[0];
        out[node] = 1.0f / (1.0f + expf(-z));
    }
}

extern "C" void kernel_launch(void* const* d_in, const int* in_sizes, int n_in,
                              void* d_out, int out_size) {
    const float* x   = (const float*)d_in[0];
    const void*  ei  = d_in[1];
    const float* W1  = (const float*)d_in[2];
    const float* b1  = (const float*)d_in[3];
    const float* W2  = (const float*)d_in[4];
    const float* b2  = (const float*)d_in[5];
    const float* W3  = (const float*)d_in[6];
    const float* b3  = (const float*)d_in[7];
    const float* g1  = (const float*)d_in[8];
    const float* be1 = (const float*)d_in[9];
    const float* m1  = (const float*)d_in[10];
    const float* v1  = (const float*)d_in[11];
    const float* g2  = (const float*)d_in[12];
    const float* be2 = (const float*)d_in[13];
    const float* m2  = (const float*)d_in[14];
    const float* v2  = (const float*)d_in[15];

    float *hs = nullptr, *act = nullptr;
    cudaGetSymbolAddress((void**)&hs, g_hs);
    cudaGetSymbolAddress((void**)&act, g_act);

    zero_deg<<<(NN + 255) / 256, 256>>>();
    detect_kernel<<<1, 256>>>((const int*)ei);
    convert_count<<<EE / 256, 256>>>(ei);
    scan_kernel<<<1, 1024>>>();
    fill_kernel<<<EE / 256, 256>>>();

    // layer 1
    gemm_dinv<128><<<(NN + 63) / 64, 256>>>(x, W1, hs);
    gather_bn_relu<<<NN / 8, 256>>>(hs, act, b1, g1, be1, m1, v1);

    // layer 2 (+ fused layer-3 projection)
    gemm_dinv<64><<<(NN + 63) / 64, 256>>>(act, W2, hs);
    gather2_dot<<<NN / 8, 256>>>(hs, b2, g2, be2, m2, v2, W3);

    // layer 3
    gather3_sigmoid<<<NN / 8, 256>>>(b3, (float*)d_out);
}

// round 4
// speedup vs baseline: 1.9034x; 1.6761x over previous
#include <cuda_runtime.h>
#include <math.h>

#define NN 100000
#define EE 3200000
#define HIDD 64
#define BN_EPS 1e-5f
#define NB 200          // scan blocks
#define CH 512          // elements per scan block (NB*CH = 102400 >= NN)

// ---- scratch (device globals; allocation-free) ----
__device__ int g_is64;
__device__ __align__(16) int   g_src[EE];
__device__ __align__(16) int   g_dst[EE];
__device__ __align__(16) int   g_deg[NN];
__device__ __align__(16) int   g_off[NN + 1];
__device__ __align__(16) int   g_cur[NN];
__device__ __align__(16) float g_dinv[NN];
__device__ __align__(16) int   g_csr[EE];
__device__ __align__(16) float g_hs[NN * HIDD];
__device__ __align__(16) float g_act[NN * HIDD];
__device__ __align__(16) float g_h3[NN];
__device__ __align__(16) int   g_bsum[NB];
__device__ __align__(16) int   g_bpre[NB];

// ---- zero degree counters ----
__global__ void zero_deg() {
    int i = blockIdx.x * blockDim.x + threadIdx.x;
    if (i < NN) g_deg[i] = 0;
}

// ---- detect edge_index dtype: int64 => odd 32-bit words all zero ----
__global__ void detect_kernel(const int* __restrict__ ei_w) {
    __shared__ int sor;
    if (threadIdx.x == 0) sor = 0;
    __syncthreads();
    int acc = 0;
    for (int i = threadIdx.x; i < 8192; i += blockDim.x)
        acc |= ei_w[2 * i + 1];
    if (acc) atomicOr(&sor, 1);
    __syncthreads();
    if (threadIdx.x == 0) g_is64 = (sor == 0) ? 1 : 0;
}

// ---- normalize edges to int32 + degree count (fused) ----
__global__ void convert_count(const void* __restrict__ ei) {
    int e = blockIdx.x * blockDim.x + threadIdx.x;
    int s, d;
    if (g_is64) {
        const long long* p = (const long long*)ei;
        s = (int)p[e]; d = (int)p[e + EE];
    } else {
        const int* p = (const int*)ei;
        s = p[e]; d = p[e + EE];
    }
    g_src[e] = s;
    g_dst[e] = d;
    if ((unsigned)d < NN) atomicAdd(&g_deg[d], 1);
}

// ---- scan phase A: per-block degree sums ----
__global__ void __launch_bounds__(CH) scanA() {
    int t = threadIdx.x;
    int i = blockIdx.x * CH + t;
    int d = (i < NN) ? g_deg[i] : 0;
    int lane = t & 31, w = t >> 5;
    int s = d;
#pragma unroll
    for (int o = 16; o > 0; o >>= 1) s += __shfl_xor_sync(0xffffffffu, s, o);
    __shared__ int ws[CH / 32];
    if (lane == 0) ws[w] = s;
    __syncthreads();
    if (t == 0) {
        int tot = 0;
#pragma unroll
        for (int k = 0; k < CH / 32; k++) tot += ws[k];
        g_bsum[blockIdx.x] = tot;
    }
}

// ---- scan phase B: scan the NB block sums (1 small block) ----
__global__ void __launch_bounds__(256) scanB() {
    __shared__ int ss[256];
    int t = threadIdx.x;
    int v = (t < NB) ? g_bsum[t] : 0;
    ss[t] = v;
    __syncthreads();
#pragma unroll
    for (int off = 1; off < 256; off <<= 1) {
        int a = (t >= off) ? ss[t - off] : 0;
        __syncthreads();
        ss[t] += a;
        __syncthreads();
    }
    if (t < NB) g_bpre[t] = ss[t] - v;      // exclusive
    if (t == NB - 1) g_off[NN] = ss[t];     // total
}

// ---- scan phase C: block-local exclusive scan + write off/cur/dinv ----
__global__ void __launch_bounds__(CH) scanC() {
    int t = threadIdx.x;
    int i = blockIdx.x * CH + t;
    int d = (i < NN) ? g_deg[i] : 0;
    int lane = t & 31, w = t >> 5;
    int x = d;
#pragma unroll
    for (int o = 1; o < 32; o <<= 1) {
        int y = __shfl_up_sync(0xffffffffu, x, o);
        if (lane >= o) x += y;
    }
    __shared__ int wsum[CH / 32];
    __shared__ int wpre[CH / 32];
    if (lane == 31) wsum[w] = x;
    __syncthreads();
    if (t == 0) {
        int run = 0;
#pragma unroll
        for (int k = 0; k < CH / 32; k++) { wpre[k] = run; run += wsum[k]; }
    }
    __syncthreads();
    if (i < NN) {
        int excl = g_bpre[blockIdx.x] + wpre[w] + x - d;
        g_off[i] = excl;
        g_cur[i] = excl;
        g_dinv[i] = rsqrtf((float)d + 1.0f);
    }
}

// ---- CSR fill using cur (pre-initialized to off) ----
__global__ void fill_kernel() {
    int e = blockIdx.x * blockDim.x + threadIdx.x;
    int d = g_dst[e];
    if ((unsigned)d >= NN) return;
    int s = g_src[e];
    if ((unsigned)s >= NN) return;
    int pos = atomicAdd(&g_cur[d], 1);
    g_csr[pos] = s;
}

// ---- GEMM: out[n,64] = (X[n,:K] @ W[K,64]) * dinv[n]
// 64-row tiles, broadcast-x, FFMA2 packed fp32 math, conflict-free smem.
template <int K>
__global__ void __launch_bounds__(256) gemm_dinv(const float* __restrict__ X,
                                                 const float* __restrict__ W,
                                                 float* __restrict__ out) {
    __shared__ float Xs[64][68];
    __shared__ float Ws[64][64];
    const int t = threadIdx.x;
    const int lane = t & 31;
    const int w = t >> 5;
    const int row0 = blockIdx.x * 64;
    const int rbase = w * 8 + ((lane >> 4) << 2);  // 4 rows per thread
    const int c4 = lane & 15;

    unsigned long long acc[4][2];
#pragma unroll
    for (int j = 0; j < 4; j++) { acc[j][0] = 0ull; acc[j][1] = 0ull; }

    const int HALVES = K / 64;
    for (int h = 0; h < HALVES; h++) {
#pragma unroll
        for (int p = 0; p < 4; p++) {
            int idx = t + p * 256;
            int kk = idx >> 4, q = idx & 15;
            reinterpret_cast<float4*>(&Ws[kk][0])[q] =
                reinterpret_cast<const float4*>(W)[(size_t)(h * 64 + kk) * 16 + q];
        }
#pragma unroll
        for (int p = 0; p < 4; p++) {
            int idx = t + p * 256;
            int r = idx >> 4, q = idx & 15;
            int gr = row0 + r; if (gr >= NN) gr = NN - 1;
            reinterpret_cast<float4*>(&Xs[r][0])[q] =
                reinterpret_cast<const float4*>(X)[(size_t)gr * (K / 4) + h * 16 + q];
        }
        __syncthreads();

        unsigned wb = (unsigned)__cvta_generic_to_shared(&Ws[0][c4 * 4]);
#pragma unroll 16
        for (int kk = 0; kk < 64; kk++) {
            unsigned long long w01, w23;
            asm("ld.shared.v2.u64 {%0, %1}, [%2];"
                : "=l"(w01), "=l"(w23) : "r"(wb + kk * 256));
#pragma unroll
            for (int j = 0; j < 4; j++) {
                float xv = Xs[rbase + j][kk];
                unsigned long long xx;
                asm("mov.b64 %0, {%1, %1};" : "=l"(xx) : "f"(xv));
                asm("fma.rn.f32x2 %0, %1, %2, %3;"
                    : "=l"(acc[j][0]) : "l"(xx), "l"(w01), "l"(acc[j][0]));
                asm("fma.rn.f32x2 %0, %1, %2, %3;"
                    : "=l"(acc[j][1]) : "l"(xx), "l"(w23), "l"(acc[j][1]));
            }
        }
        __syncthreads();
    }

#pragma unroll
    for (int j = 0; j < 4; j++) {
        int r = row0 + rbase + j;
        if (r < NN) {
            float d = g_dinv[r];
            float lo, hi;
            float4 o;
            asm("mov.b64 {%0, %1}, %2;" : "=f"(lo), "=f"(hi) : "l"(acc[j][0]));
            o.x = lo * d; o.y = hi * d;
            asm("mov.b64 {%0, %1}, %2;" : "=f"(lo), "=f"(hi) : "l"(acc[j][1]));
            o.z = lo * d; o.w = hi * d;
            reinterpret_cast<float4*>(out)[(size_t)r * 16 + c4] = o;
        }
    }
}

// ---- gather + self-loop + bias + BN + ReLU, warp per node ----
__global__ void __launch_bounds__(256) gather_bn_relu(const float* __restrict__ hs,
                                                      float* __restrict__ out,
                                                      const float* __restrict__ b,
                                                      const float* __restrict__ g,
                                                      const float* __restrict__ beta,
                                                      const float* __restrict__ m,
                                                      const float* __restrict__ v) {
    int warp = threadIdx.x >> 5;
    int lane = threadIdx.x & 31;
    int node = blockIdx.x * 8 + warp;
    if (node >= NN) return;

    const float2* hs2 = reinterpret_cast<const float2*>(hs);
    float2 acc = hs2[(size_t)node * 32 + lane];   // self-loop (already *dinv[node])
    int e0 = g_off[node], e1 = g_off[node + 1];
#pragma unroll 4
    for (int e = e0; e < e1; e++) {
        int s = g_csr[e];
        float2 xx = hs2[(size_t)s * 32 + lane];
        acc.x += xx.x; acc.y += xx.y;
    }
    float di = g_dinv[node];
    int k0 = lane * 2;
    float s0 = g[k0] * rsqrtf(v[k0] + BN_EPS);
    float s1 = g[k0 + 1] * rsqrtf(v[k0 + 1] + BN_EPS);
    float z0 = (acc.x * di + b[k0]     - m[k0])     * s0 + beta[k0];
    float z1 = (acc.y * di + b[k0 + 1] - m[k0 + 1]) * s1 + beta[k0 + 1];
    float2 o = make_float2(fmaxf(z0, 0.f), fmaxf(z1, 0.f));
    reinterpret_cast<float2*>(out)[(size_t)node * 32 + lane] = o;
}

// ---- layer-2 gather + BN + ReLU + fused W3 dot -> g_h3 ----
__global__ void __launch_bounds__(256) gather2_dot(const float* __restrict__ hs,
                                                   const float* __restrict__ b,
                                                   const float* __restrict__ g,
                                                   const float* __restrict__ beta,
                                                   const float* __restrict__ m,
                                                   const float* __restrict__ v,
                                                   const float* __restrict__ W3) {
    int warp = threadIdx.x >> 5;
    int lane = threadIdx.x & 31;
    int node = blockIdx.x * 8 + warp;
    if (node >= NN) return;

    const float2* hs2 = reinterpret_cast<const float2*>(hs);
    float2 acc = hs2[(size_t)node * 32 + lane];
    int e0 = g_off[node], e1 = g_off[node + 1];
#pragma unroll 4
    for (int e = e0; e < e1; e++) {
        int s = g_csr[e];
        float2 xx = hs2[(size_t)s * 32 + lane];
        acc.x += xx.x; acc.y += xx.y;
    }
    float di = g_dinv[node];
    int k0 = lane * 2;
    float s0 = g[k0] * rsqrtf(v[k0] + BN_EPS);
    float s1 = g[k0 + 1] * rsqrtf(v[k0 + 1] + BN_EPS);
    float z0 = (acc.x * di + b[k0]     - m[k0])     * s0 + beta[k0];
    float z1 = (acc.y * di + b[k0 + 1] - m[k0 + 1]) * s1 + beta[k0 + 1];
    float o0 = fmaxf(z0, 0.f), o1 = fmaxf(z1, 0.f);

    float2 w3 = reinterpret_cast<const float2*>(W3)[lane];
    float part = o0 * w3.x + o1 * w3.y;
#pragma unroll
    for (int o = 16; o > 0; o >>= 1) part += __shfl_xor_sync(0xffffffffu, part, o);
    if (lane == 0) g_h3[node] = part * di;
}

// ---- layer-3 gather + sigmoid, warp per node ----
__global__ void __launch_bounds__(256) gather3_sigmoid(const float* __restrict__ b3,
                                                       float* __restrict__ out) {
    int warp = threadIdx.x >> 5;
    int lane = threadIdx.x & 31;
    int node = blockIdx.x * 8 + warp;
    if (node >= NN) return;
    int e0 = g_off[node], e1 = g_off[node + 1];
    float a = 0.f;
    for (int e = e0 + lane; e < e1; e += 32) a += g_h3[g_csr[e]];
#pragma unroll
    for (int o = 16; o > 0; o >>= 1) a += __shfl_xor_sync(0xffffffffu, a, o);
    if (lane == 0) {
        float z = (a + g_h3[node]) * g_dinv[node] + b3[0];
        out[node] = 1.0f / (1.0f + expf(-z));
    }
}

extern "C" void kernel_launch(void* const* d_in, const int* in_sizes, int n_in,
                              void* d_out, int out_size) {
    const float* x   = (const float*)d_in[0];
    const void*  ei  = d_in[1];
    const float* W1  = (const float*)d_in[2];
    const float* b1  = (const float*)d_in[3];
    const float* W2  = (const float*)d_in[4];
    const float* b2  = (const float*)d_in[5];
    const float* W3  = (const float*)d_in[6];
    const float* b3  = (const float*)d_in[7];
    const float* g1  = (const float*)d_in[8];
    const float* be1 = (const float*)d_in[9];
    const float* m1  = (const float*)d_in[10];
    const float* v1  = (const float*)d_in[11];
    const float* g2  = (const float*)d_in[12];
    const float* be2 = (const float*)d_in[13];
    const float* m2  = (const float*)d_in[14];
    const float* v2  = (const float*)d_in[15];

    float *hs = nullptr, *act = nullptr;
    cudaGetSymbolAddress((void**)&hs, g_hs);
    cudaGetSymbolAddress((void**)&act, g_act);

    zero_deg<<<(NN + 255) / 256, 256>>>();
    detect_kernel<<<1, 256>>>((const int*)ei);
    convert_count<<<EE / 256, 256>>>(ei);
    scanA<<<NB, CH>>>();
    scanB<<<1, 256>>>();
    scanC<<<NB, CH>>>();
    fill_kernel<<<EE / 256, 256>>>();

    // layer 1
    gemm_dinv<128><<<(NN + 63) / 64, 256>>>(x, W1, hs);
    gather_bn_relu<<<NN / 8, 256>>>(hs, act, b1, g1, be1, m1, v1);

    // layer 2 (+ fused layer-3 projection)
    gemm_dinv<64><<<(NN + 63) / 64, 256>>>(act, W2, hs);
    gather2_dot<<<NN / 8, 256>>>(hs, b2, g2, be2, m2, v2, W3);

    // layer 3
    gather3_sigmoid<<<NN / 8, 256>>>(b3, (float*)d_out);
}

// round 5
// speedup vs baseline: 1.9775x; 1.0389x over previous
#include <cuda_runtime.h>
#include <cuda_fp16.h>
#include <math.h>

#define NN 100000
#define EE 3200000
#define HIDD 64
#define BN_EPS 1e-5f
#define NB 200          // scan blocks
#define CH 512          // elements per scan block (NB*CH = 102400 >= NN)

// ---- scratch (device globals; allocation-free) ----
__device__ int g_is64;
__device__ __align__(16) int     g_deg[NN];
__device__ __align__(16) int     g_off[NN + 1];
__device__ __align__(16) int     g_cur[NN];
__device__ __align__(16) float   g_dinv[NN];
__device__ __align__(16) int     g_csr[EE];
__device__ __align__(16) __half2 g_hsh[NN * 32];   // fp16 messages (64 dims = 32 half2)
__device__ __align__(16) float   g_act[NN * HIDD];
__device__ __align__(16) float   g_h3[NN];
__device__ __align__(16) int     g_bsum[NB];
__device__ __align__(16) int     g_bpre[NB];

// ---- zero degree counters ----
__global__ void zero_deg() {
    int i = blockIdx.x * blockDim.x + threadIdx.x;
    if (i < NN) g_deg[i] = 0;
}

// ---- detect edge_index dtype: int64 => odd 32-bit words all zero ----
__global__ void detect_kernel(const int* __restrict__ ei_w) {
    __shared__ int sor;
    if (threadIdx.x == 0) sor = 0;
    __syncthreads();
    int acc = 0;
    for (int i = threadIdx.x; i < 8192; i += blockDim.x)
        acc |= ei_w[2 * i + 1];
    if (acc) atomicOr(&sor, 1);
    __syncthreads();
    if (threadIdx.x == 0) g_is64 = (sor == 0) ? 1 : 0;
}

// ---- degree count, reading dst straight from edge_index (4 edges/thread) ----
__global__ void __launch_bounds__(256) count_kernel(const void* __restrict__ ei) {
    int i = blockIdx.x * blockDim.x + threadIdx.x;   // [0, EE/4)
    int d0, d1, d2, d3;
    if (g_is64) {
        const longlong2* p = (const longlong2*)ei + (EE / 2);  // dst block
        longlong2 a = p[2 * i], b = p[2 * i + 1];
        d0 = (int)a.x; d1 = (int)a.y; d2 = (int)b.x; d3 = (int)b.y;
    } else {
        const int4* p = (const int4*)((const int*)ei + EE);
        int4 a = p[i];
        d0 = a.x; d1 = a.y; d2 = a.z; d3 = a.w;
    }
    if ((unsigned)d0 < NN) atomicAdd(&g_deg[d0], 1);
    if ((unsigned)d1 < NN) atomicAdd(&g_deg[d1], 1);
    if ((unsigned)d2 < NN) atomicAdd(&g_deg[d2], 1);
    if ((unsigned)d3 < NN) atomicAdd(&g_deg[d3], 1);
}

// ---- scan phase A: per-block degree sums ----
__global__ void __launch_bounds__(CH) scanA() {
    int t = threadIdx.x;
    int i = blockIdx.x * CH + t;
    int d = (i < NN) ? g_deg[i] : 0;
    int lane = t & 31, w = t >> 5;
    int s = d;
#pragma unroll
    for (int o = 16; o > 0; o >>= 1) s += __shfl_xor_sync(0xffffffffu, s, o);
    __shared__ int ws[CH / 32];
    if (lane == 0) ws[w] = s;
    __syncthreads();
    if (t == 0) {
        int tot = 0;
#pragma unroll
        for (int k = 0; k < CH / 32; k++) tot += ws[k];
        g_bsum[blockIdx.x] = tot;
    }
}

// ---- scan phase B: scan the NB block sums ----
__global__ void __launch_bounds__(256) scanB() {
    __shared__ int ss[256];
    int t = threadIdx.x;
    int v = (t < NB) ? g_bsum[t] : 0;
    ss[t] = v;
    __syncthreads();
#pragma unroll
    for (int off = 1; off < 256; off <<= 1) {
        int a = (t >= off) ? ss[t - off] : 0;
        __syncthreads();
        ss[t] += a;
        __syncthreads();
    }
    if (t < NB) g_bpre[t] = ss[t] - v;
    if (t == NB - 1) g_off[NN] = ss[t];
}

// ---- scan phase C: block-local exclusive scan + off/cur/dinv ----
__global__ void __launch_bounds__(CH) scanC() {
    int t = threadIdx.x;
    int i = blockIdx.x * CH + t;
    int d = (i < NN) ? g_deg[i] : 0;
    int lane = t & 31, w = t >> 5;
    int x = d;
#pragma unroll
    for (int o = 1; o < 32; o <<= 1) {
        int y = __shfl_up_sync(0xffffffffu, x, o);
        if (lane >= o) x += y;
    }
    __shared__ int wsum[CH / 32];
    __shared__ int wpre[CH / 32];
    if (lane == 31) wsum[w] = x;
    __syncthreads();
    if (t == 0) {
        int run = 0;
#pragma unroll
        for (int k = 0; k < CH / 32; k++) { wpre[k] = run; run += wsum[k]; }
    }
    __syncthreads();
    if (i < NN) {
        int excl = g_bpre[blockIdx.x] + wpre[w] + x - d;
        g_off[i] = excl;
        g_cur[i] = excl;
        g_dinv[i] = rsqrtf((float)d + 1.0f);
    }
}

// ---- CSR fill, reading src/dst straight from edge_index (4 edges/thread) ----
__global__ void __launch_bounds__(256) fill_kernel(const void* __restrict__ ei) {
    int i = blockIdx.x * blockDim.x + threadIdx.x;   // [0, EE/4)
    int s0, s1, s2, s3, d0, d1, d2, d3;
    if (g_is64) {
        const longlong2* ps = (const longlong2*)ei;
        const longlong2* pd = ps + (EE / 2);
        longlong2 a = ps[2 * i], b = ps[2 * i + 1];
        longlong2 c = pd[2 * i], e = pd[2 * i + 1];
        s0 = (int)a.x; s1 = (int)a.y; s2 = (int)b.x; s3 = (int)b.y;
        d0 = (int)c.x; d1 = (int)c.y; d2 = (int)e.x; d3 = (int)e.y;
    } else {
        const int4* ps = (const int4*)ei;
        const int4* pd = (const int4*)((const int*)ei + EE);
        int4 a = ps[i], c = pd[i];
        s0 = a.x; s1 = a.y; s2 = a.z; s3 = a.w;
        d0 = c.x; d1 = c.y; d2 = c.z; d3 = c.w;
    }
    if ((unsigned)d0 < NN && (unsigned)s0 < NN) g_csr[atomicAdd(&g_cur[d0], 1)] = s0;
    if ((unsigned)d1 < NN && (unsigned)s1 < NN) g_csr[atomicAdd(&g_cur[d1], 1)] = s1;
    if ((unsigned)d2 < NN && (unsigned)s2 < NN) g_csr[atomicAdd(&g_cur[d2], 1)] = s2;
    if ((unsigned)d3 < NN && (unsigned)s3 < NN) g_csr[atomicAdd(&g_cur[d3], 1)] = s3;
}

// ---- GEMM: hsh[n,64] = fp16((X[n,:K] @ W[K,64]) * dinv[n]) ----
template <int K>
__global__ void __launch_bounds__(256) gemm_dinv(const float* __restrict__ X,
                                                 const float* __restrict__ W,
                                                 __half2* __restrict__ out) {
    __shared__ float Xs[64][68];
    __shared__ float Ws[64][64];
    const int t = threadIdx.x;
    const int lane = t & 31;
    const int w = t >> 5;
    const int row0 = blockIdx.x * 64;
    const int rbase = w * 8 + ((lane >> 4) << 2);  // 4 rows per thread
    const int c4 = lane & 15;

    unsigned long long acc[4][2];
#pragma unroll
    for (int j = 0; j < 4; j++) { acc[j][0] = 0ull; acc[j][1] = 0ull; }

    const int HALVES = K / 64;
    for (int h = 0; h < HALVES; h++) {
#pragma unroll
        for (int p = 0; p < 4; p++) {
            int idx = t + p * 256;
            int kk = idx >> 4, q = idx & 15;
            reinterpret_cast<float4*>(&Ws[kk][0])[q] =
                reinterpret_cast<const float4*>(W)[(size_t)(h * 64 + kk) * 16 + q];
        }
#pragma unroll
        for (int p = 0; p < 4; p++) {
            int idx = t + p * 256;
            int r = idx >> 4, q = idx & 15;
            int gr = row0 + r; if (gr >= NN) gr = NN - 1;
            reinterpret_cast<float4*>(&Xs[r][0])[q] =
                reinterpret_cast<const float4*>(X)[(size_t)gr * (K / 4) + h * 16 + q];
        }
        __syncthreads();

        unsigned wb = (unsigned)__cvta_generic_to_shared(&Ws[0][c4 * 4]);
#pragma unroll 16
        for (int kk = 0; kk < 64; kk++) {
            unsigned long long w01, w23;
            asm("ld.shared.v2.u64 {%0, %1}, [%2];"
                : "=l"(w01), "=l"(w23) : "r"(wb + kk * 256));
#pragma unroll
            for (int j = 0; j < 4; j++) {
                float xv = Xs[rbase + j][kk];
                unsigned long long xx;
                asm("mov.b64 %0, {%1, %1};" : "=l"(xx) : "f"(xv));
                asm("fma.rn.f32x2 %0, %1, %2, %3;"
                    : "=l"(acc[j][0]) : "l"(xx), "l"(w01), "l"(acc[j][0]));
                asm("fma.rn.f32x2 %0, %1, %2, %3;"
                    : "=l"(acc[j][1]) : "l"(xx), "l"(w23), "l"(acc[j][1]));
            }
        }
        __syncthreads();
    }

#pragma unroll
    for (int j = 0; j < 4; j++) {
        int r = row0 + rbase + j;
        if (r < NN) {
            float d = g_dinv[r];
            float lo, hi;
            asm("mov.b64 {%0, %1}, %2;" : "=f"(lo), "=f"(hi) : "l"(acc[j][0]));
            __half2 h01 = __float22half2_rn(make_float2(lo * d, hi * d));
            asm("mov.b64 {%0, %1}, %2;" : "=f"(lo), "=f"(hi) : "l"(acc[j][1]));
            __half2 h23 = __float22half2_rn(make_float2(lo * d, hi * d));
            uint2 packed;
            packed.x = *reinterpret_cast<unsigned*>(&h01);
            packed.y = *reinterpret_cast<unsigned*>(&h23);
            reinterpret_cast<uint2*>(out)[(size_t)r * 16 + c4] = packed;
        }
    }
}

// ---- gather (fp16 msgs, fp32 accum) + bias + BN + ReLU, warp per node ----
__global__ void __launch_bounds__(256) gather_bn_relu(const __half2* __restrict__ hs,
                                                      float* __restrict__ out,
                                                      const float* __restrict__ b,
                                                      const float* __restrict__ g,
                                                      const float* __restrict__ beta,
                                                      const float* __restrict__ m,
                                                      const float* __restrict__ v) {
    int warp = threadIdx.x >> 5;
    int lane = threadIdx.x & 31;
    int node = blockIdx.x * 8 + warp;
    if (node >= NN) return;

    float2 acc = __half22float2(hs[(size_t)node * 32 + lane]);  // self-loop term
    int e0 = g_off[node], e1 = g_off[node + 1];
#pragma unroll 4
    for (int e = e0; e < e1; e++) {
        int s = g_csr[e];
        float2 xx = __half22float2(hs[(size_t)s * 32 + lane]);
        acc.x += xx.x; acc.y += xx.y;
    }
    float di = g_dinv[node];
    int k0 = lane * 2;
    float s0 = g[k0] * rsqrtf(v[k0] + BN_EPS);
    float s1 = g[k0 + 1] * rsqrtf(v[k0 + 1] + BN_EPS);
    float z0 = (acc.x * di + b[k0]     - m[k0])     * s0 + beta[k0];
    float z1 = (acc.y * di + b[k0 + 1] - m[k0 + 1]) * s1 + beta[k0 + 1];
    float2 o = make_float2(fmaxf(z0, 0.f), fmaxf(z1, 0.f));
    reinterpret_cast<float2*>(out)[(size_t)node * 32 + lane] = o;
}

// ---- layer-2 gather + BN + ReLU + fused W3 dot -> g_h3 ----
__global__ void __launch_bounds__(256) gather2_dot(const __half2* __restrict__ hs,
                                                   const float* __restrict__ b,
                                                   const float* __restrict__ g,
                                                   const float* __restrict__ beta,
                                                   const float* __restrict__ m,
                                                   const float* __restrict__ v,
                                                   const float* __restrict__ W3) {
    int warp = threadIdx.x >> 5;
    int lane = threadIdx.x & 31;
    int node = blockIdx.x * 8 + warp;
    if (node >= NN) return;

    float2 acc = __half22float2(hs[(size_t)node * 32 + lane]);
    int e0 = g_off[node], e1 = g_off[node + 1];
#pragma unroll 4
    for (int e = e0; e < e1; e++) {
        int s = g_csr[e];
        float2 xx = __half22float2(hs[(size_t)s * 32 + lane]);
        acc.x += xx.x; acc.y += xx.y;
    }
    float di = g_dinv[node];
    int k0 = lane * 2;
    float s0 = g[k0] * rsqrtf(v[k0] + BN_EPS);
    float s1 = g[k0 + 1] * rsqrtf(v[k0 + 1] + BN_EPS);
    float z0 = (acc.x * di + b[k0]     - m[k0])     * s0 + beta[k0];
    float z1 = (acc.y * di + b[k0 + 1] - m[k0 + 1]) * s1 + beta[k0 + 1];
    float o0 = fmaxf(z0, 0.f), o1 = fmaxf(z1, 0.f);

    float2 w3 = reinterpret_cast<const float2*>(W3)[lane];
    float part = o0 * w3.x + o1 * w3.y;
#pragma unroll
    for (int o = 16; o > 0; o >>= 1) part += __shfl_xor_sync(0xffffffffu, part, o);
    if (lane == 0) g_h3[node] = part * di;
}

// ---- layer-3 gather + sigmoid, warp per node ----
__global__ void __launch_bounds__(256) gather3_sigmoid(const float* __restrict__ b3,
                                                       float* __restrict__ out) {
    int warp = threadIdx.x >> 5;
    int lane = threadIdx.x & 31;
    int node = blockIdx.x * 8 + warp;
    if (node >= NN) return;
    int e0 = g_off[node], e1 = g_off[node + 1];
    float a = 0.f;
    for (int e = e0 + lane; e < e1; e += 32) a += g_h3[g_csr[e]];
#pragma unroll
    for (int o = 16; o > 0; o >>= 1) a += __shfl_xor_sync(0xffffffffu, a, o);
    if (lane == 0) {
        float z = (a + g_h3[node]) * g_dinv[node] + b3[0];
        out[node] = 1.0f / (1.0f + expf(-z));
    }
}

extern "C" void kernel_launch(void* const* d_in, const int* in_sizes, int n_in,
                              void* d_out, int out_size) {
    const float* x   = (const float*)d_in[0];
    const void*  ei  = d_in[1];
    const float* W1  = (const float*)d_in[2];
    const float* b1  = (const float*)d_in[3];
    const float* W2  = (const float*)d_in[4];
    const float* b2  = (const float*)d_in[5];
    const float* W3  = (const float*)d_in[6];
    const float* b3  = (const float*)d_in[7];
    const float* g1  = (const float*)d_in[8];
    const float* be1 = (const float*)d_in[9];
    const float* m1  = (const float*)d_in[10];
    const float* v1  = (const float*)d_in[11];
    const float* g2  = (const float*)d_in[12];
    const float* be2 = (const float*)d_in[13];
    const float* m2  = (const float*)d_in[14];
    const float* v2  = (const float*)d_in[15];

    __half2* hsh = nullptr; float* act = nullptr;
    cudaGetSymbolAddress((void**)&hsh, g_hsh);
    cudaGetSymbolAddress((void**)&act, g_act);

    zero_deg<<<(NN + 255) / 256, 256>>>();
    detect_kernel<<<1, 256>>>((const int*)ei);
    count_kernel<<<EE / 4 / 256, 256>>>(ei);
    scanA<<<NB, CH>>>();
    scanB<<<1, 256>>>();
    scanC<<<NB, CH>>>();
    fill_kernel<<<EE / 4 / 256, 256>>>(ei);

    // layer 1
    gemm_dinv<128><<<(NN + 63) / 64, 256>>>(x, W1, hsh);
    gather_bn_relu<<<NN / 8, 256>>>(hsh, act, b1, g1, be1, m1, v1);

    // layer 2 (+ fused layer-3 projection)
    gemm_dinv<64><<<(NN + 63) / 64, 256>>>(act, W2, hsh);
    gather2_dot<<<NN / 8, 256>>>(hsh, b2, g2, be2, m2, v2, W3);

    // layer 3
    gather3_sigmoid<<<NN / 8, 256>>>(b3, (float*)d_out);
}